// round 16
// baseline (speedup 1.0000x reference)
#include <cuda_runtime.h>

#define BB 4096
#define TT 200
#define DD 128
#define KS 5
#define NTHREADS 256

__device__ __forceinline__ float warp_sum(float v) {
#pragma unroll
    for (int o = 16; o; o >>= 1) v += __shfl_xor_sync(0xffffffffu, v, o);
    return v;
}

__global__ void __launch_bounds__(NTHREADS, 4)
user_enc_kernel(const float* __restrict__ items_g,
                const int* __restrict__ mask_g,
                const float* __restrict__ age_g,
                const float* __restrict__ pop_g,
                const float* __restrict__ Wq,
                const float* __restrict__ Wk,
                const float* __restrict__ Wv,
                const float* __restrict__ gate_w,
                const float* __restrict__ gate_b,
                const float* __restrict__ ln_g,
                const float* __restrict__ ln_b,
                const float* __restrict__ dalpha,
                float* __restrict__ out) {
    __shared__ float s_mask[TT];
    __shared__ float s_age[TT];
    __shared__ float s_pop[TT];
    __shared__ float s_dlog[TT];
    __shared__ float s_mean[DD];
    __shared__ float s_q[DD];
    __shared__ float s_r[DD];
    __shared__ float s_w[DD];
    __shared__ float s_lt[DD];
    __shared__ float s_part[1024];
    __shared__ float s_wm[8];
    __shared__ float s_wz[8];
    __shared__ float s_red[8];
    __shared__ float s_scal[4];

    const int tid  = threadIdx.x;
    const int lane = tid & 31;
    const int warp = tid >> 5;
    const int b    = blockIdx.x;
    const float NEG_INF = __int_as_float(0xff800000);
    const float* row = items_g + (size_t)b * TT * DD;
    const float4* row4 = (const float4*)row;

    // ---- phase 0: metadata + decay-log (parallel) ----
    const float alpha = log1pf(expf(dalpha[0])) + 1e-6f;
    if (tid < TT) {
        int m = mask_g[(size_t)b * TT + tid];
        float a = age_g[(size_t)b * TT + tid];
        s_mask[tid] = m ? 1.f : 0.f;
        s_age[tid]  = a;
        s_pop[tid]  = pop_g[(size_t)b * TT + tid];
        s_dlog[tid] = m ? __logf(__expf(-alpha * a) + 1e-12f) : NEG_INF;
    }
    __syncthreads();

    // ---- pass 1 (DRAM): masked mean accumulation ----
    {
        float4 acc = make_float4(0.f, 0.f, 0.f, 0.f);
#pragma unroll
        for (int k = 0; k < (TT * DD / 4) / NTHREADS; ++k) {  // 25
            int i = tid + k * NTHREADS;
            float4 v = row4[i];
            float m = s_mask[i >> 5];
            acc.x += m * v.x; acc.y += m * v.y; acc.z += m * v.z; acc.w += m * v.w;
        }
        ((float4*)s_part)[tid] = acc;
        if (warp == 0) {
            float c = 0.f;
            for (int t = lane; t < TT; t += 32) c += s_mask[t];
            c = warp_sum(c);
            if (lane == 0) s_scal[0] = c;
        }
    }
    __syncthreads();
    const float cntf = s_scal[0];

    if (tid < DD) {
        int d4 = tid >> 2, comp = tid & 3;
        float s = 0.f;
#pragma unroll
        for (int j = 0; j < 8; ++j)
            s += s_part[(j * 32 + d4) * 4 + comp];
        s_mean[tid] = s / (cntf + 1e-6f);
    }
    __syncthreads();

    // ---- q[i] = dot(Wq row i, mean): warp-per-i, coalesced L2/L1 ----
    {
        float4 mv = ((const float4*)s_mean)[lane];
#pragma unroll
        for (int k = 0; k < 16; ++k) {
            int i = warp + k * 8;
            float4 w4 = ((const float4*)(Wq + (size_t)i * DD))[lane];
            float d = w4.x * mv.x + w4.y * mv.y + w4.z * mv.z + w4.w * mv.w;
            d = warp_sum(d);
            if (lane == 0) s_q[i] = d;
        }
    }
    __syncthreads();

    // ---- r[d] = sum_i q[i]*Wk[i,d], i split over halves, coalesced ----
    {
        int e = tid & 127, half = tid >> 7;
        const float* Kp = Wk + (size_t)half * 64 * DD + e;
        const float* qp = s_q + half * 64;
        float r = 0.f;
#pragma unroll 16
        for (int i = 0; i < 64; ++i)
            r += qp[i] * Kp[(size_t)i * DD];
        s_part[half * DD + e] = r;
    }
    __syncthreads();
    if (tid < DD) s_r[tid] = s_part[tid] + s_part[DD + tid];
    __syncthreads();

    // ---- pass 2 (L2): fused scores + online softmax + weighted sum ----
    const float scale = 0.08838834764831845f;  // 1/sqrt(128)
    {
        float4 rv = ((const float4*)s_r)[lane];
        float m = NEG_INF, Z = 0.f;
        float4 acc = make_float4(0.f, 0.f, 0.f, 0.f);
#pragma unroll
        for (int kb = 0; kb < 5; ++kb) {
            float4 xv[5];
            float  dt[5];
#pragma unroll
            for (int j = 0; j < 5; ++j) {
                int t = warp + (kb * 5 + j) * 8;
                xv[j] = row4[t * 32 + lane];
            }
#pragma unroll
            for (int j = 0; j < 5; ++j) {
                float d = xv[j].x * rv.x + xv[j].y * rv.y +
                          xv[j].z * rv.z + xv[j].w * rv.w;
                dt[j] = warp_sum(d);
            }
#pragma unroll
            for (int j = 0; j < 5; ++j) {
                int t = warp + (kb * 5 + j) * 8;
                float dl = s_dlog[t];
                if (dl != NEG_INF) {
                    float s = dt[j] * scale + dl;
                    if (s > m) {
                        float c = __expf(m - s);
                        Z *= c;
                        acc.x *= c; acc.y *= c; acc.z *= c; acc.w *= c;
                        m = s;
                    }
                    float p = __expf(s - m);
                    Z += p;
                    acc.x += p * xv[j].x; acc.y += p * xv[j].y;
                    acc.z += p * xv[j].z; acc.w += p * xv[j].w;
                }
            }
        }
        ((float4*)s_part)[warp * 32 + lane] = acc;
        if (lane == 0) { s_wm[warp] = m; s_wz[warp] = Z; }
    }
    __syncthreads();

    // ---- merge warp states -> normalized w in smem ----
    if (tid < DD) {
        float M = s_wm[0];
#pragma unroll
        for (int j = 1; j < 8; ++j) M = fmaxf(M, s_wm[j]);
        float Zt = 0.f, w = 0.f;
#pragma unroll
        for (int j = 0; j < 8; ++j) {
            float f = __expf(s_wm[j] - M);
            Zt += f * s_wz[j];
            w  += f * s_part[j * DD + tid];
        }
        s_w[tid] = w / Zt;
    }
    __syncthreads();

    // ---- long_term[e] = sum_d Wv[e,d] * w[d]  (warp-per-e, L2 coalesced) ----
    {
        float4 wv4 = ((const float4*)s_w)[lane];
#pragma unroll 4
        for (int e = warp; e < DD; e += 8) {
            float4 m4 = ((const float4*)(Wv + (size_t)e * DD))[lane];
            float dot = m4.x * wv4.x + m4.y * wv4.y + m4.z * wv4.z + m4.w * wv4.w;
            dot = warp_sum(dot);
            if (lane == 0) s_lt[e] = dot;
        }
    }
    __syncthreads();

    // ---- short-term window (L2-hot rows), gate, combine ----
    float u = 0.f;
    if (tid < DD) {
        int cnt = (int)(cntf + 0.5f);
        if (cnt < 1) cnt = 1;
        int start = cnt - KS;
        if (start < 0) start = 0;
        float dn = (float)(cnt - start);

        float st = 0.f;
        for (int t = start; t < cnt; ++t) st += row[t * DD + tid];
        st /= dn;

        float mp = 0.f, mr = 0.f;
        for (int t = start; t < cnt; ++t) { mp += s_pop[t]; mr += s_age[t]; }
        mp /= dn; mr /= dn;

        float z = mp * gate_w[0] + mr * gate_w[1] + gate_b[0];
        float g = 1.f / (1.f + __expf(-z));
        u = g * st + (1.f - g) * s_lt[tid];
    }

    // ---- block LN over 128 values (warps 0-3 hold them) ----
    {
        float v1 = (tid < DD) ? u : 0.f;
        v1 = warp_sum(v1);
        if (lane == 0) s_red[warp] = v1;
        __syncthreads();
        float mu = (s_red[0] + s_red[1] + s_red[2] + s_red[3]) * (1.f / 128.f);
        __syncthreads();
        float d2 = (tid < DD) ? (u - mu) * (u - mu) : 0.f;
        d2 = warp_sum(d2);
        if (lane == 0) s_red[warp] = d2;
        __syncthreads();
        float var = (s_red[0] + s_red[1] + s_red[2] + s_red[3]) * (1.f / 128.f);
        if (tid < DD) {
            float o = (u - mu) * rsqrtf(var + 1e-5f) * ln_g[tid] + ln_b[tid];
            out[(size_t)b * DD + tid] = o;
        }
    }
}

extern "C" void kernel_launch(void* const* d_in, const int* in_sizes, int n_in,
                              void* d_out, int out_size) {
    const float* items = (const float*)d_in[0];
    const int*   mask  = (const int*)d_in[1];
    const float* age   = (const float*)d_in[2];
    const float* pop   = (const float*)d_in[3];
    const float* Wq    = (const float*)d_in[4];
    const float* Wk    = (const float*)d_in[5];
    const float* Wv    = (const float*)d_in[6];
    const float* gw    = (const float*)d_in[7];
    const float* gb    = (const float*)d_in[8];
    const float* lng   = (const float*)d_in[9];
    const float* lnb   = (const float*)d_in[10];
    const float* da    = (const float*)d_in[11];
    float* out = (float*)d_out;

    user_enc_kernel<<<BB, NTHREADS>>>(items, mask, age, pop, Wq, Wk, Wv,
                                      gw, gb, lng, lnb, da, out);
}